// round 3
// baseline (speedup 1.0000x reference)
#include <cuda_runtime.h>
#include <cstdint>

// DifferentiableDAG: B*T independent 8-step log-space DAG executions.
// One thread per element. WARP-PRIVATE staging: each warp cp.asyncs its own
// 32 elements' per-step chunk into its own smem region and syncs with
// cp.async.wait_group + __syncwarp only (no block barriers).
// Exploits structural zeros: step s needs only operand probs 0..s.

constexpr int TPB  = 128;
constexpr int ST   = 25;              // floats per smem row (23 used; odd => conflict-free)
constexpr int WBUF = 32 * ST;         // floats per warp per buffer (800)
constexpr int BUF  = 4 * WBUF;        // per-block buffer (4 warps)

__device__ __forceinline__ void cp_async4(uint32_t saddr, const void* gaddr) {
    asm volatile("cp.async.ca.shared.global [%0], [%1], 4;\n" :: "r"(saddr), "l"(gaddr));
}
__device__ __forceinline__ void cp_commit() { asm volatile("cp.async.commit_group;\n"); }
template<int N>
__device__ __forceinline__ void cp_wait() { asm volatile("cp.async.wait_group %0;\n" :: "n"(N) : "memory"); }

// clip_log(x) = 15*tanh(x/15) via (1-e^{-2z})/(1+e^{-2z})
__device__ __forceinline__ float clip_log(float x) {
    float a = fabsf(x) * (2.0f / 15.0f);
    float t = __expf(-a);
    float u = __fdividef(1.0f - t, 1.0f + t);
    return copysignf(15.0f * u, x);
}

// Stage step S for this warp's 32 elements: p1[0..S], p2[0..S], pop[0..4].
template<int S>
__device__ __forceinline__ void issue_chunk(
    uint32_t sbuf, const float* __restrict__ p1, const float* __restrict__ p2,
    const float* __restrict__ pop, int W0, int lane, int elems)
{
    constexpr int NF = S + 1;
#pragma unroll
    for (int k = 0; k < NF; k++) {
        int i = lane + 32 * k;            // 0 .. 32*NF-1
        int e = i / NF, q = i - NF * e;
        if (W0 + e < elems) {
            int g = (W0 + e) * 72 + S * 9 + q;
            cp_async4(sbuf + 4u * (uint32_t)(e * ST + q),     p1 + g);
            cp_async4(sbuf + 4u * (uint32_t)(e * ST + 9 + q), p2 + g);
        }
    }
#pragma unroll
    for (int k = 0; k < 5; k++) {
        int i = lane + 32 * k;
        int e = i / 5, q = i - 5 * e;
        if (W0 + e < elems)
            cp_async4(sbuf + 4u * (uint32_t)(e * ST + 18 + q),
                      pop + (W0 + e) * 40 + S * 5 + q);
    }
}

template<int S>
__device__ __forceinline__ void step_compute(
    const float* __restrict__ row, float (&sg)[9], float (&lg)[9], float& acc)
{
    // ---- dot products over live nodes 0..S ----
    float s1v = 0.f, l1v = 0.f, s2v = 0.f, l2v = 0.f;
#pragma unroll
    for (int n = 0; n <= S; n++) {
        float a = row[n];
        float b = row[9 + n];
        s1v = fmaf(a, sg[n], s1v);
        l1v = fmaf(a, lg[n], l1v);
        s2v = fmaf(b, sg[n], s2v);
        l2v = fmaf(b, lg[n], l2v);
    }
    float po0 = row[18], po1 = row[19], po2 = row[20], po3 = row[21], po4 = row[22];

    // ---- shared log-magnitude pieces (identical for add and sub) ----
    float dlt    = l1v - l2v;
    float m      = fmaxf(l1v, l2v);
    float l_same = clip_log(m + __logf(1.0f + __expf(-fabsf(dlt))));
    bool  bigger = (l1v >= l2v);
    float big_l  = bigger ? l1v : l2v;
    float small_l = bigger ? l2v : l1v;
    float delta  = fminf(fmaxf(small_l - big_l, -15.0f), -0.001f);
    float diffv  = __logf(1.0f - __expf(delta));     // log1p(-exp(delta)), arg in [1e-3,1)
    bool  zr     = (small_l == big_l);
    float new_l  = zr ? 0.0f : (big_l + diffv);

    bool  z1 = (s1v == 0.0f), z2 = (s2v == 0.0f);
    float prod = s1v * s2v;
    float s_sgn1 = (s1v > 0.f) ? 1.f : ((s1v < 0.f) ? -1.f : 0.f);

    // ---- ADD ----
    float sa = 0.f, la = 0.f;
    {
        bool same_sign = (prod > 0.0f);
        float big_s = bigger ? s1v : s2v;
        float new_s = zr ? 0.0f : big_s;
        if (!z1 &&  z2) { sa = s1v; la = l1v; }
        if ( z1 && !z2) { sa = s2v; la = l2v; }
        if (!z1 && !z2) {
            if (same_sign) { sa = s_sgn1; la = l_same; }
            else           { sa = new_s;  la = new_l;  }
        }
        la = clip_log(la);
    }
    // ---- SUB (sy = -s2v) ----
    float sb = 0.f, lb = 0.f;
    {
        bool same_sign = (prod < 0.0f);
        float sy = -s2v;
        float big_s = bigger ? s1v : sy;
        float new_s = zr ? 0.0f : big_s;
        if (!z1 &&  z2) { sb = s1v; lb = l1v; }
        if ( z1 && !z2) { sb = sy;  lb = l2v; }
        if (!z1 && !z2) {
            if (same_sign) { sb = s_sgn1; lb = l_same; }
            else           { sb = new_s;  lb = new_l;  }
        }
        lb = clip_log(lb);
    }
    // ---- MUL / DIV / ID ----
    float lm = clip_log(l1v + l2v);
    float ld = clip_log(dlt);

    // ---- probability mix ----
    float s_mix = po0 * sa;
    s_mix = fmaf(po1, sb,   s_mix);
    s_mix = fmaf(po2, prod, s_mix);
    s_mix = fmaf(po3, prod, s_mix);
    s_mix = fmaf(po4, s1v,  s_mix);
    float l_mix = po0 * la;
    l_mix = fmaf(po1, lb,  l_mix);
    l_mix = fmaf(po2, lm,  l_mix);
    l_mix = fmaf(po3, ld,  l_mix);
    l_mix = fmaf(po4, l1v, l_mix);
    l_mix = clip_log(l_mix);

    // ---- incremental RMS rescale over logs[0..S] + l_mix ----
    float cur = fmaf(l_mix, l_mix, acc);
    constexpr float inv = 1.0f / (float)(S + 2);
    float r     = rsqrtf(cur * inv + 1e-6f);
    float scale = fminf(15.0f * r, 1.0f);
    l_mix *= scale;

    sg[S + 1] = s_mix;
    lg[S + 1] = l_mix;
    acc = fmaf(l_mix, l_mix, acc);
}

__global__ void __launch_bounds__(TPB, 8)
dag_kernel(const float* __restrict__ isgn, const float* __restrict__ ilog,
           const float* __restrict__ p1,   const float* __restrict__ p2,
           const float* __restrict__ pop,  float* __restrict__ out, int elems)
{
    __shared__ float smem[2 * BUF];

    const int t    = threadIdx.x;
    const int lane = t & 31;
    const int w    = t >> 5;
    const int E0   = blockIdx.x * TPB;
    const int W0   = E0 + w * 32;        // this warp's first element
    const int e    = W0 + lane;          // this thread's element

    // Hoist the two initial scalar loads so their latency overlaps the prologue.
    float seed_s = 0.f, seed_l = 0.f;
    if (e < elems) {
        seed_s = isgn[(size_t)e * 9];
        seed_l = ilog[(size_t)e * 9];
    }

    uint32_t sA = (uint32_t)__cvta_generic_to_shared(smem) + 4u * (uint32_t)(w * WBUF);
    uint32_t sB = sA + 4u * BUF;

    // Prologue: chunks 0 and 1 for this warp only.
    issue_chunk<0>(sA, p1, p2, pop, W0, lane, elems); cp_commit();
    issue_chunk<1>(sB, p1, p2, pop, W0, lane, elems); cp_commit();

    // Only node 0 of the initial state is nonzero (by construction).
    float sg[9], lg[9];
#pragma unroll
    for (int j = 0; j < 9; j++) { sg[j] = 0.f; lg[j] = 0.f; }
    sg[0] = seed_s;
    lg[0] = seed_l;
    float acc = lg[0] * lg[0];

    const float* rowA = smem + w * WBUF + lane * ST;
    const float* rowB = rowA + BUF;

    // s=0
    cp_wait<1>(); __syncwarp();
    step_compute<0>(rowA, sg, lg, acc);
    __syncwarp();
    issue_chunk<2>(sA, p1, p2, pop, W0, lane, elems); cp_commit();
    // s=1
    cp_wait<1>(); __syncwarp();
    step_compute<1>(rowB, sg, lg, acc);
    __syncwarp();
    issue_chunk<3>(sB, p1, p2, pop, W0, lane, elems); cp_commit();
    // s=2
    cp_wait<1>(); __syncwarp();
    step_compute<2>(rowA, sg, lg, acc);
    __syncwarp();
    issue_chunk<4>(sA, p1, p2, pop, W0, lane, elems); cp_commit();
    // s=3
    cp_wait<1>(); __syncwarp();
    step_compute<3>(rowB, sg, lg, acc);
    __syncwarp();
    issue_chunk<5>(sB, p1, p2, pop, W0, lane, elems); cp_commit();
    // s=4
    cp_wait<1>(); __syncwarp();
    step_compute<4>(rowA, sg, lg, acc);
    __syncwarp();
    issue_chunk<6>(sA, p1, p2, pop, W0, lane, elems); cp_commit();
    // s=5
    cp_wait<1>(); __syncwarp();
    step_compute<5>(rowB, sg, lg, acc);
    __syncwarp();
    issue_chunk<7>(sB, p1, p2, pop, W0, lane, elems); cp_commit();
    // s=6
    cp_wait<1>(); __syncwarp();
    step_compute<6>(rowA, sg, lg, acc);
    // s=7 (drain)
    cp_wait<0>(); __syncwarp();
    step_compute<7>(rowB, sg, lg, acc);

    if (e < elems)
        out[e] = sg[8] * __expf(lg[8]);
}

extern "C" void kernel_launch(void* const* d_in, const int* in_sizes, int n_in,
                              void* d_out, int out_size)
{
    const float* isgn = (const float*)d_in[0];
    const float* ilog = (const float*)d_in[1];
    const float* p1   = (const float*)d_in[2];
    const float* p2   = (const float*)d_in[3];
    const float* pop  = (const float*)d_in[4];
    float* out = (float*)d_out;

    int elems  = in_sizes[0] / 9;               // B*T
    int blocks = (elems + TPB - 1) / TPB;
    dag_kernel<<<blocks, TPB>>>(isgn, ilog, p1, p2, pop, out, elems);
}

// round 4
// speedup vs baseline: 2.3373x; 2.3373x over previous
#include <cuda_runtime.h>
#include <cstdint>

// DifferentiableDAG: B*T independent 8-step log-space DAG executions.
// One thread per element. WARP-PRIVATE staging: each warp cp.asyncs its own
// 32 elements' per-step chunk into its own smem region and syncs with
// cp.async.wait_group + __syncwarp only (no block barriers).
// Exploits structural zeros: step s needs only operand probs 0..s.
// R4: __launch_bounds__(TPB,6) — R3's forced 64-reg cap spilled the state
// arrays and serialized every step on LDL; 80 regs / 6 blocks is the sweet spot.

constexpr int TPB  = 128;
constexpr int ST   = 25;              // floats per smem row (23 used; odd => conflict-free)
constexpr int WBUF = 32 * ST;         // floats per warp per buffer (800)
constexpr int BUF  = 4 * WBUF;        // per-block buffer (4 warps)

__device__ __forceinline__ void cp_async4(uint32_t saddr, const void* gaddr) {
    asm volatile("cp.async.ca.shared.global [%0], [%1], 4;\n" :: "r"(saddr), "l"(gaddr));
}
__device__ __forceinline__ void cp_commit() { asm volatile("cp.async.commit_group;\n"); }
template<int N>
__device__ __forceinline__ void cp_wait() { asm volatile("cp.async.wait_group %0;\n" :: "n"(N) : "memory"); }

// clip_log(x) = 15*tanh(x/15) via (1-e^{-2z})/(1+e^{-2z})
__device__ __forceinline__ float clip_log(float x) {
    float a = fabsf(x) * (2.0f / 15.0f);
    float t = __expf(-a);
    float u = __fdividef(1.0f - t, 1.0f + t);
    return copysignf(15.0f * u, x);
}

// Stage step S for this warp's 32 elements: p1[0..S], p2[0..S], pop[0..4].
template<int S>
__device__ __forceinline__ void issue_chunk(
    uint32_t sbuf, const float* __restrict__ p1, const float* __restrict__ p2,
    const float* __restrict__ pop, int W0, int lane, int elems)
{
    constexpr int NF = S + 1;
#pragma unroll
    for (int k = 0; k < NF; k++) {
        int i = lane + 32 * k;            // 0 .. 32*NF-1
        int e = i / NF, q = i - NF * e;
        if (W0 + e < elems) {
            int g = (W0 + e) * 72 + S * 9 + q;
            cp_async4(sbuf + 4u * (uint32_t)(e * ST + q),     p1 + g);
            cp_async4(sbuf + 4u * (uint32_t)(e * ST + 9 + q), p2 + g);
        }
    }
#pragma unroll
    for (int k = 0; k < 5; k++) {
        int i = lane + 32 * k;
        int e = i / 5, q = i - 5 * e;
        if (W0 + e < elems)
            cp_async4(sbuf + 4u * (uint32_t)(e * ST + 18 + q),
                      pop + (W0 + e) * 40 + S * 5 + q);
    }
}

template<int S>
__device__ __forceinline__ void step_compute(
    const float* __restrict__ row, float (&sg)[9], float (&lg)[9], float& acc)
{
    // ---- dot products over live nodes 0..S ----
    float s1v = 0.f, l1v = 0.f, s2v = 0.f, l2v = 0.f;
#pragma unroll
    for (int n = 0; n <= S; n++) {
        float a = row[n];
        float b = row[9 + n];
        s1v = fmaf(a, sg[n], s1v);
        l1v = fmaf(a, lg[n], l1v);
        s2v = fmaf(b, sg[n], s2v);
        l2v = fmaf(b, lg[n], l2v);
    }
    float po0 = row[18], po1 = row[19], po2 = row[20], po3 = row[21], po4 = row[22];

    // ---- shared log-magnitude pieces (identical for add and sub) ----
    float dlt    = l1v - l2v;
    float m      = fmaxf(l1v, l2v);
    float l_same = clip_log(m + __logf(1.0f + __expf(-fabsf(dlt))));
    bool  bigger = (l1v >= l2v);
    float big_l  = bigger ? l1v : l2v;
    float small_l = bigger ? l2v : l1v;
    float delta  = fminf(fmaxf(small_l - big_l, -15.0f), -0.001f);
    float diffv  = __logf(1.0f - __expf(delta));     // log1p(-exp(delta)), arg in [1e-3,1)
    bool  zr     = (small_l == big_l);
    float new_l  = zr ? 0.0f : (big_l + diffv);

    bool  z1 = (s1v == 0.0f), z2 = (s2v == 0.0f);
    float prod = s1v * s2v;
    float s_sgn1 = (s1v > 0.f) ? 1.f : ((s1v < 0.f) ? -1.f : 0.f);

    // ---- ADD ----
    float sa = 0.f, la = 0.f;
    {
        bool same_sign = (prod > 0.0f);
        float big_s = bigger ? s1v : s2v;
        float new_s = zr ? 0.0f : big_s;
        if (!z1 &&  z2) { sa = s1v; la = l1v; }
        if ( z1 && !z2) { sa = s2v; la = l2v; }
        if (!z1 && !z2) {
            if (same_sign) { sa = s_sgn1; la = l_same; }
            else           { sa = new_s;  la = new_l;  }
        }
        la = clip_log(la);
    }
    // ---- SUB (sy = -s2v) ----
    float sb = 0.f, lb = 0.f;
    {
        bool same_sign = (prod < 0.0f);
        float sy = -s2v;
        float big_s = bigger ? s1v : sy;
        float new_s = zr ? 0.0f : big_s;
        if (!z1 &&  z2) { sb = s1v; lb = l1v; }
        if ( z1 && !z2) { sb = sy;  lb = l2v; }
        if (!z1 && !z2) {
            if (same_sign) { sb = s_sgn1; lb = l_same; }
            else           { sb = new_s;  lb = new_l;  }
        }
        lb = clip_log(lb);
    }
    // ---- MUL / DIV / ID ----
    float lm = clip_log(l1v + l2v);
    float ld = clip_log(dlt);

    // ---- probability mix ----
    float s_mix = po0 * sa;
    s_mix = fmaf(po1, sb,   s_mix);
    s_mix = fmaf(po2, prod, s_mix);
    s_mix = fmaf(po3, prod, s_mix);
    s_mix = fmaf(po4, s1v,  s_mix);
    float l_mix = po0 * la;
    l_mix = fmaf(po1, lb,  l_mix);
    l_mix = fmaf(po2, lm,  l_mix);
    l_mix = fmaf(po3, ld,  l_mix);
    l_mix = fmaf(po4, l1v, l_mix);
    l_mix = clip_log(l_mix);

    // ---- incremental RMS rescale over logs[0..S] + l_mix ----
    float cur = fmaf(l_mix, l_mix, acc);
    constexpr float inv = 1.0f / (float)(S + 2);
    float r     = rsqrtf(cur * inv + 1e-6f);
    float scale = fminf(15.0f * r, 1.0f);
    l_mix *= scale;

    sg[S + 1] = s_mix;
    lg[S + 1] = l_mix;
    acc = fmaf(l_mix, l_mix, acc);
}

__global__ void __launch_bounds__(TPB, 6)
dag_kernel(const float* __restrict__ isgn, const float* __restrict__ ilog,
           const float* __restrict__ p1,   const float* __restrict__ p2,
           const float* __restrict__ pop,  float* __restrict__ out, int elems)
{
    __shared__ float smem[2 * BUF];

    const int t    = threadIdx.x;
    const int lane = t & 31;
    const int w    = t >> 5;
    const int E0   = blockIdx.x * TPB;
    const int W0   = E0 + w * 32;        // this warp's first element
    const int e    = W0 + lane;          // this thread's element

    // Hoist the two initial scalar loads so their latency overlaps the prologue.
    float seed_s = 0.f, seed_l = 0.f;
    if (e < elems) {
        seed_s = isgn[(size_t)e * 9];
        seed_l = ilog[(size_t)e * 9];
    }

    uint32_t sA = (uint32_t)__cvta_generic_to_shared(smem) + 4u * (uint32_t)(w * WBUF);
    uint32_t sB = sA + 4u * BUF;

    // Prologue: chunks 0 and 1 for this warp only.
    issue_chunk<0>(sA, p1, p2, pop, W0, lane, elems); cp_commit();
    issue_chunk<1>(sB, p1, p2, pop, W0, lane, elems); cp_commit();

    // Only node 0 of the initial state is nonzero (by construction).
    float sg[9], lg[9];
#pragma unroll
    for (int j = 0; j < 9; j++) { sg[j] = 0.f; lg[j] = 0.f; }
    sg[0] = seed_s;
    lg[0] = seed_l;
    float acc = lg[0] * lg[0];

    const float* rowA = smem + w * WBUF + lane * ST;
    const float* rowB = rowA + BUF;

    // s=0
    cp_wait<1>(); __syncwarp();
    step_compute<0>(rowA, sg, lg, acc);
    __syncwarp();
    issue_chunk<2>(sA, p1, p2, pop, W0, lane, elems); cp_commit();
    // s=1
    cp_wait<1>(); __syncwarp();
    step_compute<1>(rowB, sg, lg, acc);
    __syncwarp();
    issue_chunk<3>(sB, p1, p2, pop, W0, lane, elems); cp_commit();
    // s=2
    cp_wait<1>(); __syncwarp();
    step_compute<2>(rowA, sg, lg, acc);
    __syncwarp();
    issue_chunk<4>(sA, p1, p2, pop, W0, lane, elems); cp_commit();
    // s=3
    cp_wait<1>(); __syncwarp();
    step_compute<3>(rowB, sg, lg, acc);
    __syncwarp();
    issue_chunk<5>(sB, p1, p2, pop, W0, lane, elems); cp_commit();
    // s=4
    cp_wait<1>(); __syncwarp();
    step_compute<4>(rowA, sg, lg, acc);
    __syncwarp();
    issue_chunk<6>(sA, p1, p2, pop, W0, lane, elems); cp_commit();
    // s=5
    cp_wait<1>(); __syncwarp();
    step_compute<5>(rowB, sg, lg, acc);
    __syncwarp();
    issue_chunk<7>(sB, p1, p2, pop, W0, lane, elems); cp_commit();
    // s=6
    cp_wait<1>(); __syncwarp();
    step_compute<6>(rowA, sg, lg, acc);
    // s=7 (drain)
    cp_wait<0>(); __syncwarp();
    step_compute<7>(rowB, sg, lg, acc);

    if (e < elems)
        out[e] = sg[8] * __expf(lg[8]);
}

extern "C" void kernel_launch(void* const* d_in, const int* in_sizes, int n_in,
                              void* d_out, int out_size)
{
    const float* isgn = (const float*)d_in[0];
    const float* ilog = (const float*)d_in[1];
    const float* p1   = (const float*)d_in[2];
    const float* p2   = (const float*)d_in[3];
    const float* pop  = (const float*)d_in[4];
    float* out = (float*)d_out;

    int elems  = in_sizes[0] / 9;               // B*T
    int blocks = (elems + TPB - 1) / TPB;
    dag_kernel<<<blocks, TPB>>>(isgn, ilog, p1, p2, pop, out, elems);
}